// round 1
// baseline (speedup 1.0000x reference)
#include <cuda_runtime.h>

// InfluenceProp: B=4096 samples, K=50 neighbors, E=128.
// One CTA per sample. All neighbor activations live in SMEM; weights staged
// in 128x128 chunks into SMEM and reused across the 50 rows.
// fp32 CUDA-core GEMM, register tile 7(M) x 4(N) per thread, 256 threads.

#define K_N 50
#define E_N 128
#define ROWS_PAD 56           // 50 rows padded to 56 (ty + 8*j, j<7)
#define SSTR 264              // activation row stride (floats), 16B-aligned
#define WSTR 132              // weight row stride (floats), 16B-aligned

__device__ __forceinline__ void gemm50(
    const float* __restrict__ gW,   // [Kin][128] row-major in gmem
    const float* __restrict__ gB,   // [128] bias
    const float* __restrict__ sIn,  // activation buffer, row stride SSTR, cols [0,Kin)
    int Kin,
    float* __restrict__ sOut, int outOff,
    float* __restrict__ sW, int tid)
{
    const int tx = tid & 31;
    const int ty = tid >> 5;

    float acc[7][4];
#pragma unroll
    for (int j = 0; j < 7; ++j) {
        acc[j][0] = 0.f; acc[j][1] = 0.f; acc[j][2] = 0.f; acc[j][3] = 0.f;
    }

    for (int ch = 0; ch < Kin; ch += 128) {
        __syncthreads();   // previous users of sW / previous layer writes done
        // stage 128x128 weight chunk into SMEM (float4, padded stride)
#pragma unroll
        for (int t = 0; t < 16; ++t) {
            int idx = tid + t * 256;
            int row = idx >> 5;
            int c4  = idx & 31;
            *(float4*)(sW + row * WSTR + c4 * 4) =
                *(const float4*)(gW + (size_t)(ch + row) * 128 + c4 * 4);
        }
        __syncthreads();

        const float* inBase = sIn + ch;
#pragma unroll 4
        for (int i = 0; i < 128; ++i) {
            float4 w = *(const float4*)(sW + i * WSTR + tx * 4);
#pragma unroll
            for (int j = 0; j < 7; ++j) {
                float a = inBase[(ty + 8 * j) * SSTR + i];   // broadcast within warp
                acc[j][0] = fmaf(a, w.x, acc[j][0]);
                acc[j][1] = fmaf(a, w.y, acc[j][1]);
                acc[j][2] = fmaf(a, w.z, acc[j][2]);
                acc[j][3] = fmaf(a, w.w, acc[j][3]);
            }
        }
    }

    float4 bias = *(const float4*)(gB + tx * 4);
#pragma unroll
    for (int j = 0; j < 7; ++j) {
        int r = ty + 8 * j;
        if (r < K_N) {
            float4 o;
            o.x = fmaxf(acc[j][0] + bias.x, 0.f);
            o.y = fmaxf(acc[j][1] + bias.y, 0.f);
            o.z = fmaxf(acc[j][2] + bias.z, 0.f);
            o.w = fmaxf(acc[j][3] + bias.w, 0.f);
            *(float4*)(sOut + r * SSTR + outOff + tx * 4) = o;
        }
    }
}

__global__ __launch_bounds__(256, 1)
void influence_kernel(
    const float* __restrict__ u_embs,     // [B,128]
    const float* __restrict__ i_embs,     // [B,128]
    const int*   __restrict__ act_users,  // [B,50]
    const float* __restrict__ emb_table,  // [NU,128]
    const float* __restrict__ prof_table, // [NU,128]
    const float* __restrict__ w_fus, const float* __restrict__ b_fus,
    const float* __restrict__ w_c1,  const float* __restrict__ b_c1,
    const float* __restrict__ w_c2,  const float* __restrict__ b_c2,
    const float* __restrict__ w_a1,  const float* __restrict__ b_a1,
    const float* __restrict__ w_a2,  const float* __restrict__ b_a2,
    const float* __restrict__ w_a3,  const float* __restrict__ b_a3,
    float* __restrict__ out_combined,     // [B,128]
    float* __restrict__ out_att)          // [B,50]
{
    extern __shared__ float smem[];
    float* bufA   = smem;                         // [56][264]
    float* bufB   = bufA + ROWS_PAD * SSTR;       // [56][264]
    float* sW     = bufB + ROWS_PAD * SSTR;       // [128][132]
    float* sScore = sW + 128 * WSTR;              // [64]
    float* sAtt   = sScore + 64;                  // [64]
    int*   sIdx   = (int*)(sAtt + 64);            // [64]

    const int b   = blockIdx.x;
    const int tid = threadIdx.x;

    // stage neighbor indices; zero the padding rows (50..55) of both buffers
    if (tid < K_N) sIdx[tid] = act_users[(size_t)b * K_N + tid];
    for (int idx = tid; idx < (ROWS_PAD - K_N) * 256; idx += 256) {
        int r = K_N + idx / 256;
        int c = idx & 255;
        bufA[r * SSTR + c] = 0.f;
        bufB[r * SSTR + c] = 0.f;
    }
    __syncthreads();

    // gather: bufA[k][0..127]=emb, [128..255]=prof   (float4, coalesced per row)
    for (int idx = tid; idx < K_N * 64; idx += 256) {
        int k = idx >> 6;
        int q = idx & 63;
        int u = sIdx[k];
        float4 v;
        if (q < 32)
            v = *(const float4*)(emb_table + (size_t)u * 128 + q * 4);
        else
            v = *(const float4*)(prof_table + (size_t)u * 128 + (q - 32) * 4);
        *(float4*)(bufA + k * SSTR + q * 4) = v;
    }
    // bufB[k][128..255] = i_emb[b] (broadcast over k) — L2 input second half
    for (int idx = tid; idx < K_N * 32; idx += 256) {
        int k = idx >> 5;
        int q = idx & 31;
        *(float4*)(bufB + k * SSTR + 128 + q * 4) =
            *(const float4*)(i_embs + (size_t)b * 128 + q * 4);
    }
    __syncthreads();

    // L1: fused = relu([emb|prof] @ w_fus + b)     -> bufB[:,0..127]
    gemm50(w_fus, b_fus, bufA, 256, bufB, 0, sW, tid);
    __syncthreads();
    // L2: c1 = relu([fused|i_emb] @ w_c1 + b)      -> bufA[:,0..127]
    gemm50(w_c1, b_c1, bufB, 256, bufA, 0, sW, tid);
    __syncthreads();
    // refill bufB[:,128..255] = u_emb[b] (L2 done reading i_emb region)
    for (int idx = tid; idx < K_N * 32; idx += 256) {
        int k = idx >> 5;
        int q = idx & 31;
        *(float4*)(bufB + k * SSTR + 128 + q * 4) =
            *(const float4*)(u_embs + (size_t)b * 128 + q * 4);
    }
    // L3: coup = relu(c1 @ w_c2 + b)               -> bufB[:,0..127]  (kept!)
    gemm50(w_c2, b_c2, bufA, 128, bufB, 0, sW, tid);
    __syncthreads();
    // L4: h = relu([coup|u_emb] @ w_a1 + b)        -> bufA[:,0..127]
    gemm50(w_a1, b_a1, bufB, 256, bufA, 0, sW, tid);
    __syncthreads();
    // L5: h2 = relu(h @ w_a2 + b)                  -> bufA[:,128..255]
    gemm50(w_a2, b_a2, bufA, 128, bufA, 128, sW, tid);
    __syncthreads();

    // L6: scores[k] = h2[k] . w_a3 + b_a3    (warp per k)
    {
        int warp = tid >> 5, lane = tid & 31;
        for (int k = warp; k < K_N; k += 8) {
            float p = 0.f;
#pragma unroll
            for (int t = 0; t < 4; ++t) {
                int i = lane + 32 * t;
                p = fmaf(bufA[k * SSTR + 128 + i], w_a3[i], p);
            }
#pragma unroll
            for (int o = 16; o; o >>= 1)
                p += __shfl_xor_sync(0xffffffffu, p, o);
            if (lane == 0) sScore[k] = p + b_a3[0];
        }
    }
    __syncthreads();

    // softmax over 50 scores (warp 0)
    if (tid < 32) {
        float v1 = (tid < K_N)      ? sScore[tid]      : -1e30f;
        float v2 = (tid + 32 < K_N) ? sScore[tid + 32] : -1e30f;
        float m = fmaxf(v1, v2);
#pragma unroll
        for (int o = 16; o; o >>= 1)
            m = fmaxf(m, __shfl_xor_sync(0xffffffffu, m, o));
        float e1 = (tid < K_N)      ? expf(v1 - m) : 0.f;
        float e2 = (tid + 32 < K_N) ? expf(v2 - m) : 0.f;
        float s = e1 + e2;
#pragma unroll
        for (int o = 16; o; o >>= 1)
            s += __shfl_xor_sync(0xffffffffu, s, o);
        float inv = 1.f / s;
        if (tid < K_N)      sAtt[tid]      = e1 * inv;
        if (tid + 32 < K_N) sAtt[tid + 32] = e2 * inv;
    }
    __syncthreads();

    // combined[e] = sum_k att[k] * coup[k][e]  (coup in bufB[:,0..127])
    if (tid < 128) {
        float s = 0.f;
#pragma unroll
        for (int k = 0; k < K_N; ++k)
            s = fmaf(sAtt[k], bufB[k * SSTR + tid], s);
        out_combined[(size_t)b * 128 + tid] = s;
    }
    if (tid >= 128 && tid < 128 + K_N)
        out_att[(size_t)b * K_N + (tid - 128)] = sAtt[tid - 128];
}

extern "C" void kernel_launch(void* const* d_in, const int* in_sizes, int n_in,
                              void* d_out, int out_size) {
    // metadata order:
    // 0 users(unused) 1 u_embs 2 items(unused) 3 i_embs 4 act_users
    // 5 user_emb_table 6 user_profiles
    // 7 w_fus 8 b_fus 9 w_c1 10 b_c1 11 w_c2 12 b_c2
    // 13 w_a1 14 b_a1 15 w_a2 16 b_a2 17 w_a3 18 b_a3
    const float* u_embs = (const float*)d_in[1];
    const float* i_embs = (const float*)d_in[3];
    const int*   act    = (const int*)d_in[4];
    const float* table  = (const float*)d_in[5];
    const float* prof   = (const float*)d_in[6];
    const float* w_fus  = (const float*)d_in[7];
    const float* b_fus  = (const float*)d_in[8];
    const float* w_c1   = (const float*)d_in[9];
    const float* b_c1   = (const float*)d_in[10];
    const float* w_c2   = (const float*)d_in[11];
    const float* b_c2   = (const float*)d_in[12];
    const float* w_a1   = (const float*)d_in[13];
    const float* b_a1   = (const float*)d_in[14];
    const float* w_a2   = (const float*)d_in[15];
    const float* b_a2   = (const float*)d_in[16];
    const float* w_a3   = (const float*)d_in[17];
    const float* b_a3   = (const float*)d_in[18];

    int B = in_sizes[0];   // 4096

    float* out_combined = (float*)d_out;
    float* out_att      = out_combined + (size_t)B * E_N;  // [combined | att]

    size_t smem_bytes = (size_t)(2 * ROWS_PAD * SSTR + 128 * WSTR + 192) * sizeof(float);
    cudaFuncSetAttribute(influence_kernel,
                         cudaFuncAttributeMaxDynamicSharedMemorySize,
                         (int)smem_bytes);

    influence_kernel<<<B, 256, smem_bytes>>>(
        u_embs, i_embs, act, table, prof,
        w_fus, b_fus, w_c1, b_c1, w_c2, b_c2,
        w_a1, b_a1, w_a2, b_a2, w_a3, b_a3,
        out_combined, out_att);
}

// round 2
// speedup vs baseline: 1.6114x; 1.6114x over previous
#include <cuda_runtime.h>

// InfluenceProp R2: one CTA per sample, 256 threads, 2 CTAs/SM.
// - float4 activation + weight loads: 11 LDS per 112 FFMA in the inner loop
// - broadcast concat halves (i_emb, u_emb) folded into per-layer bias vector
//   via a cheap matvec -> row-GEMM K drops 256->128 for layers c1, a1
// - 64-row weight chunks in SMEM (reused across all 50 neighbor rows)

#define K_N 50
#define E_N 128
#define ROWS_PAD 56          // 50 rows padded (row = ty + 8*j, j<7)
#define ASTR 132             // activation row stride (floats), 16B aligned
#define WSTR 132             // weight row stride (floats)

// GEMM: out[r][n] = relu( sum_k in[r][k] * W[k][n] + vec[n] ), r<50, n<128.
// K = nChunks*64. Chunks 0,1 read in0 (+0,+64); chunks 2,3 read in1 (+0,+64).
__device__ __forceinline__ void gemm50(
    const float* __restrict__ gW, int nChunks,
    const float* __restrict__ in0, const float* __restrict__ in1,
    const float* __restrict__ sVec,
    float* __restrict__ sOut,
    float* __restrict__ sW, int tid)
{
    const int tx = tid & 31;
    const int ty = tid >> 5;

    float acc[7][4];
#pragma unroll
    for (int j = 0; j < 7; ++j) {
        acc[j][0] = 0.f; acc[j][1] = 0.f; acc[j][2] = 0.f; acc[j][3] = 0.f;
    }

    for (int c = 0; c < nChunks; ++c) {
        __syncthreads();   // prior users of sW done / prior writes visible
        const float* wsrc = gW + (size_t)c * 64 * 128;
#pragma unroll
        for (int t = 0; t < 8; ++t) {
            int idx = tid + t * 256;       // 0..2047 float4 slots
            int row = idx >> 5;            // 0..63
            int c4  = idx & 31;
            *(float4*)(sW + row * WSTR + c4 * 4) =
                *(const float4*)(wsrc + row * 128 + c4 * 4);
        }
        __syncthreads();

        const float* src = (c < 2) ? (in0 + c * 64) : (in1 + (c - 2) * 64);
#pragma unroll 4
        for (int i0 = 0; i0 < 64; i0 += 4) {
            float4 w0 = *(const float4*)(sW + (i0 + 0) * WSTR + tx * 4);
            float4 w1 = *(const float4*)(sW + (i0 + 1) * WSTR + tx * 4);
            float4 w2 = *(const float4*)(sW + (i0 + 2) * WSTR + tx * 4);
            float4 w3 = *(const float4*)(sW + (i0 + 3) * WSTR + tx * 4);
#pragma unroll
            for (int j = 0; j < 7; ++j) {
                float4 a = *(const float4*)(src + (ty + 8 * j) * ASTR + i0);
                acc[j][0] = fmaf(a.x, w0.x, acc[j][0]);
                acc[j][1] = fmaf(a.x, w0.y, acc[j][1]);
                acc[j][2] = fmaf(a.x, w0.z, acc[j][2]);
                acc[j][3] = fmaf(a.x, w0.w, acc[j][3]);
                acc[j][0] = fmaf(a.y, w1.x, acc[j][0]);
                acc[j][1] = fmaf(a.y, w1.y, acc[j][1]);
                acc[j][2] = fmaf(a.y, w1.z, acc[j][2]);
                acc[j][3] = fmaf(a.y, w1.w, acc[j][3]);
                acc[j][0] = fmaf(a.z, w2.x, acc[j][0]);
                acc[j][1] = fmaf(a.z, w2.y, acc[j][1]);
                acc[j][2] = fmaf(a.z, w2.z, acc[j][2]);
                acc[j][3] = fmaf(a.z, w2.w, acc[j][3]);
                acc[j][0] = fmaf(a.w, w3.x, acc[j][0]);
                acc[j][1] = fmaf(a.w, w3.y, acc[j][1]);
                acc[j][2] = fmaf(a.w, w3.z, acc[j][2]);
                acc[j][3] = fmaf(a.w, w3.w, acc[j][3]);
            }
        }
    }

    __syncthreads();   // allow in-place output (all reads of inputs done)
    float4 bias = *(const float4*)(sVec + tx * 4);
#pragma unroll
    for (int j = 0; j < 7; ++j) {
        int r = ty + 8 * j;
        if (r < K_N) {
            float4 o;
            o.x = fmaxf(acc[j][0] + bias.x, 0.f);
            o.y = fmaxf(acc[j][1] + bias.y, 0.f);
            o.z = fmaxf(acc[j][2] + bias.z, 0.f);
            o.w = fmaxf(acc[j][3] + bias.w, 0.f);
            *(float4*)(sOut + r * ASTR + tx * 4) = o;
        }
    }
}

// sVec[n] = sum_i sX[i] * gWbot[i][n] + gB[n]    (bottom half of a 256xE weight)
// 256 threads: col = tid&127, half = tid>>7; partial sums reduced via sTmp.
__device__ __forceinline__ void prep_vec_matvec(
    const float* __restrict__ gWbot, const float* __restrict__ gB,
    const float* __restrict__ sX, float* __restrict__ sVec,
    float* __restrict__ sTmp, int tid)
{
    int col  = tid & 127;
    int half = tid >> 7;
    float a = (half == 0) ? gB[col] : 0.f;
    int i0 = half * 64;
#pragma unroll 8
    for (int i = 0; i < 64; ++i)
        a = fmaf(sX[i0 + i], gWbot[(size_t)(i0 + i) * 128 + col], a);
    sTmp[tid] = a;
    __syncthreads();
    if (tid < 128) sVec[tid] = sTmp[tid] + sTmp[tid + 128];
}

__global__ __launch_bounds__(256, 2)
void influence_kernel(
    const float* __restrict__ u_embs,     // [B,128]
    const float* __restrict__ i_embs,     // [B,128]
    const int*   __restrict__ act_users,  // [B,50]
    const float* __restrict__ emb_table,  // [NU,128]
    const float* __restrict__ prof_table, // [NU,128]
    const float* __restrict__ w_fus, const float* __restrict__ b_fus,
    const float* __restrict__ w_c1,  const float* __restrict__ b_c1,
    const float* __restrict__ w_c2,  const float* __restrict__ b_c2,
    const float* __restrict__ w_a1,  const float* __restrict__ b_a1,
    const float* __restrict__ w_a2,  const float* __restrict__ b_a2,
    const float* __restrict__ w_a3,  const float* __restrict__ b_a3,
    float* __restrict__ out_combined,     // [B,128]
    float* __restrict__ out_att)          // [B,50]
{
    extern __shared__ float smem[];
    float* bufA   = smem;                        // [56][132]
    float* bufB   = bufA + ROWS_PAD * ASTR;      // [56][132]
    float* sW     = bufB + ROWS_PAD * ASTR;      // [64][132] (also matvec sTmp)
    float* sVec   = sW + 64 * WSTR;              // [128]
    float* sX     = sVec + 128;                  // [128]
    float* sScore = sX + 128;                    // [64]
    float* sAtt   = sScore + 64;                 // [64]
    int*   sIdx   = (int*)(sAtt + 64);           // [64]

    const int b   = blockIdx.x;
    const int tid = threadIdx.x;

    // neighbor indices; zero padding rows of both buffers
    if (tid < K_N) sIdx[tid] = act_users[(size_t)b * K_N + tid];
    for (int idx = tid; idx < (ROWS_PAD - K_N) * ASTR; idx += 256) {
        int r = K_N + idx / ASTR;
        int c = idx % ASTR;
        bufA[r * ASTR + c] = 0.f;
        bufB[r * ASTR + c] = 0.f;
    }
    // bias for layer 1 (fusion)
    if (tid < 128) sVec[tid] = b_fus[tid];
    __syncthreads();

    // gather: bufA[k] = emb row, bufB[k] = profile row (float4, coalesced)
    for (int idx = tid; idx < K_N * 64; idx += 256) {
        int k = idx >> 6;
        int q = idx & 63;
        int u = sIdx[k];
        if (q < 32) {
            *(float4*)(bufA + k * ASTR + q * 4) =
                *(const float4*)(emb_table + (size_t)u * 128 + q * 4);
        } else {
            *(float4*)(bufB + k * ASTR + (q - 32) * 4) =
                *(const float4*)(prof_table + (size_t)u * 128 + (q - 32) * 4);
        }
    }

    // L1: fused = relu([emb|prof] @ w_fus + b_fus)       -> bufA
    gemm50(w_fus, 4, bufA, bufB, sVec, bufA, sW, tid);
    __syncthreads();

    // prep: sVec = i_emb @ w_c1[128:256] + b_c1
    if (tid < 32) {
        float4 v = *(const float4*)(i_embs + (size_t)b * 128 + tid * 4);
        *(float4*)(sX + tid * 4) = v;
    }
    __syncthreads();
    prep_vec_matvec(w_c1 + (size_t)128 * 128, b_c1, sX, sVec, sW, tid);

    // L2: c1 = relu(fused @ w_c1_top + sVec)             -> bufB
    gemm50(w_c1, 2, bufA, nullptr, sVec, bufB, sW, tid);
    __syncthreads();

    if (tid < 128) sVec[tid] = b_c2[tid];
    // L3: coup = relu(c1 @ w_c2 + b_c2)                  -> bufA   (kept!)
    gemm50(w_c2, 2, bufB, nullptr, sVec, bufA, sW, tid);
    __syncthreads();

    // prep: sVec = u_emb @ w_a1[128:256] + b_a1
    if (tid < 32) {
        float4 v = *(const float4*)(u_embs + (size_t)b * 128 + tid * 4);
        *(float4*)(sX + tid * 4) = v;
    }
    __syncthreads();
    prep_vec_matvec(w_a1 + (size_t)128 * 128, b_a1, sX, sVec, sW, tid);

    // L4: h = relu(coup @ w_a1_top + sVec)               -> bufB
    gemm50(w_a1, 2, bufA, nullptr, sVec, bufB, sW, tid);
    __syncthreads();

    if (tid < 128) sVec[tid] = b_a2[tid];
    // L5: h2 = relu(h @ w_a2 + b_a2)                     -> bufB (in-place OK)
    gemm50(w_a2, 2, bufB, nullptr, sVec, bufB, sW, tid);
    __syncthreads();

    // L6: scores[k] = h2[k] . w_a3 + b_a3    (warp per k)
    {
        int warp = tid >> 5, lane = tid & 31;
        for (int k = warp; k < K_N; k += 8) {
            float p = 0.f;
#pragma unroll
            for (int t = 0; t < 4; ++t) {
                int i = lane + 32 * t;
                p = fmaf(bufB[k * ASTR + i], w_a3[i], p);
            }
#pragma unroll
            for (int o = 16; o; o >>= 1)
                p += __shfl_xor_sync(0xffffffffu, p, o);
            if (lane == 0) sScore[k] = p + b_a3[0];
        }
    }
    __syncthreads();

    // softmax over 50 scores (warp 0)
    if (tid < 32) {
        float v1 = (tid < K_N)      ? sScore[tid]      : -1e30f;
        float v2 = (tid + 32 < K_N) ? sScore[tid + 32] : -1e30f;
        float m = fmaxf(v1, v2);
#pragma unroll
        for (int o = 16; o; o >>= 1)
            m = fmaxf(m, __shfl_xor_sync(0xffffffffu, m, o));
        float e1 = (tid < K_N)      ? expf(v1 - m) : 0.f;
        float e2 = (tid + 32 < K_N) ? expf(v2 - m) : 0.f;
        float s = e1 + e2;
#pragma unroll
        for (int o = 16; o; o >>= 1)
            s += __shfl_xor_sync(0xffffffffu, s, o);
        float inv = 1.f / s;
        if (tid < K_N)      sAtt[tid]      = e1 * inv;
        if (tid + 32 < K_N) sAtt[tid + 32] = e2 * inv;
    }
    __syncthreads();

    // combined[e] = sum_k att[k] * coup[k][e]   (coup in bufA)
    if (tid < 128) {
        float s = 0.f;
#pragma unroll
        for (int k = 0; k < K_N; ++k)
            s = fmaf(sAtt[k], bufA[k * ASTR + tid], s);
        out_combined[(size_t)b * 128 + tid] = s;
    }
    if (tid >= 128 && tid < 128 + K_N)
        out_att[(size_t)b * K_N + (tid - 128)] = sAtt[tid - 128];
}

extern "C" void kernel_launch(void* const* d_in, const int* in_sizes, int n_in,
                              void* d_out, int out_size) {
    const float* u_embs = (const float*)d_in[1];
    const float* i_embs = (const float*)d_in[3];
    const int*   act    = (const int*)d_in[4];
    const float* table  = (const float*)d_in[5];
    const float* prof   = (const float*)d_in[6];
    const float* w_fus  = (const float*)d_in[7];
    const float* b_fus  = (const float*)d_in[8];
    const float* w_c1   = (const float*)d_in[9];
    const float* b_c1   = (const float*)d_in[10];
    const float* w_c2   = (const float*)d_in[11];
    const float* b_c2   = (const float*)d_in[12];
    const float* w_a1   = (const float*)d_in[13];
    const float* b_a1   = (const float*)d_in[14];
    const float* w_a2   = (const float*)d_in[15];
    const float* b_a2   = (const float*)d_in[16];
    const float* w_a3   = (const float*)d_in[17];
    const float* b_a3   = (const float*)d_in[18];

    int B = in_sizes[0];   // 4096

    float* out_combined = (float*)d_out;
    float* out_att      = out_combined + (size_t)B * E_N;

    size_t smem_bytes = (size_t)(2 * ROWS_PAD * ASTR + 64 * WSTR + 128 + 128 + 192)
                        * sizeof(float);
    cudaFuncSetAttribute(influence_kernel,
                         cudaFuncAttributeMaxDynamicSharedMemorySize,
                         (int)smem_bytes);

    influence_kernel<<<B, 256, smem_bytes>>>(
        u_embs, i_embs, act, table, prof,
        w_fus, b_fus, w_c1, b_c1, w_c2, b_c2,
        w_a1, b_a1, w_a2, b_a2, w_a3, b_a3,
        out_combined, out_att);
}

// round 3
// speedup vs baseline: 1.6151x; 1.0023x over previous
#include <cuda_runtime.h>

// InfluenceProp R3: R2 structure + packed fp32 math (fma.rn.f32x2 / FFMA2).
// Scalar FFMA-3reg caps at 2/cyc/SM on sm_103a; the packed f32x2 path doubles
// fp32 throughput. Accumulators are b64 packed column-pairs; weights load as
// ulonglong2 (two aligned f32x2 pairs, no repack); broadcast activation packs
// via one mov.b64 per scalar (ALU pipe, hidden under FMA pipe).

#define K_N 50
#define E_N 128
#define ROWS_PAD 56          // 50 rows padded (row = ty + 8*j, j<7)
#define ASTR 132             // activation row stride (floats), 16B aligned
#define WSTR 132             // weight row stride (floats)

typedef unsigned long long u64;

__device__ __forceinline__ u64 pack2s(float x) {
    u64 r;
    asm("mov.b64 %0, {%1, %1};" : "=l"(r) : "f"(x));
    return r;
}
__device__ __forceinline__ void fma2(u64& d, u64 a, u64 b) {
    asm("fma.rn.f32x2 %0, %1, %2, %0;" : "+l"(d) : "l"(a), "l"(b));
}
__device__ __forceinline__ float2 unpack2(u64 v) {
    float2 f;
    asm("mov.b64 {%0, %1}, %2;" : "=f"(f.x), "=f"(f.y) : "l"(v));
    return f;
}

// GEMM: out[r][n] = relu( sum_k in[r][k] * W[k][n] + vec[n] ), r<50, n<128.
// K = nChunks*64. Chunks 0,1 read in0 (+0,+64); chunks 2,3 read in1 (+0,+64).
__device__ __forceinline__ void gemm50(
    const float* __restrict__ gW, int nChunks,
    const float* __restrict__ in0, const float* __restrict__ in1,
    const float* __restrict__ sVec,
    float* __restrict__ sOut,
    float* __restrict__ sW, int tid)
{
    const int tx = tid & 31;
    const int ty = tid >> 5;

    u64 acc[7][2];   // packed column pairs: [0]=(4tx,4tx+1), [1]=(4tx+2,4tx+3)
#pragma unroll
    for (int j = 0; j < 7; ++j) { acc[j][0] = 0ull; acc[j][1] = 0ull; }

    for (int c = 0; c < nChunks; ++c) {
        __syncthreads();   // prior users of sW done / prior writes visible
        const float* wsrc = gW + (size_t)c * 64 * 128;
#pragma unroll
        for (int t = 0; t < 8; ++t) {
            int idx = tid + t * 256;       // 0..2047 float4 slots
            int row = idx >> 5;            // 0..63
            int c4  = idx & 31;
            *(float4*)(sW + row * WSTR + c4 * 4) =
                *(const float4*)(wsrc + row * 128 + c4 * 4);
        }
        __syncthreads();

        const float* src = (c < 2) ? (in0 + c * 64) : (in1 + (c - 2) * 64);
#pragma unroll 4
        for (int i0 = 0; i0 < 64; i0 += 4) {
            // 4 weight rows, each as two packed f32x2 (same LDS.128 as before)
            ulonglong2 w0 = *(const ulonglong2*)(sW + (i0 + 0) * WSTR + tx * 4);
            ulonglong2 w1 = *(const ulonglong2*)(sW + (i0 + 1) * WSTR + tx * 4);
            ulonglong2 w2 = *(const ulonglong2*)(sW + (i0 + 2) * WSTR + tx * 4);
            ulonglong2 w3 = *(const ulonglong2*)(sW + (i0 + 3) * WSTR + tx * 4);
#pragma unroll
            for (int j = 0; j < 7; ++j) {
                float4 a = *(const float4*)(src + (ty + 8 * j) * ASTR + i0);
                u64 p;
                p = pack2s(a.x); fma2(acc[j][0], p, w0.x); fma2(acc[j][1], p, w0.y);
                p = pack2s(a.y); fma2(acc[j][0], p, w1.x); fma2(acc[j][1], p, w1.y);
                p = pack2s(a.z); fma2(acc[j][0], p, w2.x); fma2(acc[j][1], p, w2.y);
                p = pack2s(a.w); fma2(acc[j][0], p, w3.x); fma2(acc[j][1], p, w3.y);
            }
        }
    }

    __syncthreads();   // allow in-place output (all reads of inputs done)
    float4 bias = *(const float4*)(sVec + tx * 4);
#pragma unroll
    for (int j = 0; j < 7; ++j) {
        int r = ty + 8 * j;
        if (r < K_N) {
            float2 lo = unpack2(acc[j][0]);
            float2 hi = unpack2(acc[j][1]);
            float4 o;
            o.x = fmaxf(lo.x + bias.x, 0.f);
            o.y = fmaxf(lo.y + bias.y, 0.f);
            o.z = fmaxf(hi.x + bias.z, 0.f);
            o.w = fmaxf(hi.y + bias.w, 0.f);
            *(float4*)(sOut + r * ASTR + tx * 4) = o;
        }
    }
}

// sVec[n] = sum_i sX[i] * gWbot[i][n] + gB[n]    (bottom half of a 256xE weight)
__device__ __forceinline__ void prep_vec_matvec(
    const float* __restrict__ gWbot, const float* __restrict__ gB,
    const float* __restrict__ sX, float* __restrict__ sVec,
    float* __restrict__ sTmp, int tid)
{
    int col  = tid & 127;
    int half = tid >> 7;
    float a = (half == 0) ? gB[col] : 0.f;
    int i0 = half * 64;
#pragma unroll 8
    for (int i = 0; i < 64; ++i)
        a = fmaf(sX[i0 + i], gWbot[(size_t)(i0 + i) * 128 + col], a);
    sTmp[tid] = a;
    __syncthreads();
    if (tid < 128) sVec[tid] = sTmp[tid] + sTmp[tid + 128];
}

__global__ __launch_bounds__(256, 2)
void influence_kernel(
    const float* __restrict__ u_embs,     // [B,128]
    const float* __restrict__ i_embs,     // [B,128]
    const int*   __restrict__ act_users,  // [B,50]
    const float* __restrict__ emb_table,  // [NU,128]
    const float* __restrict__ prof_table, // [NU,128]
    const float* __restrict__ w_fus, const float* __restrict__ b_fus,
    const float* __restrict__ w_c1,  const float* __restrict__ b_c1,
    const float* __restrict__ w_c2,  const float* __restrict__ b_c2,
    const float* __restrict__ w_a1,  const float* __restrict__ b_a1,
    const float* __restrict__ w_a2,  const float* __restrict__ b_a2,
    const float* __restrict__ w_a3,  const float* __restrict__ b_a3,
    float* __restrict__ out_combined,     // [B,128]
    float* __restrict__ out_att)          // [B,50]
{
    extern __shared__ float smem[];
    float* bufA   = smem;                        // [56][132]
    float* bufB   = bufA + ROWS_PAD * ASTR;      // [56][132]
    float* sW     = bufB + ROWS_PAD * ASTR;      // [64][132] (also matvec sTmp)
    float* sVec   = sW + 64 * WSTR;              // [128]
    float* sX     = sVec + 128;                  // [128]
    float* sScore = sX + 128;                    // [64]
    float* sAtt   = sScore + 64;                 // [64]
    int*   sIdx   = (int*)(sAtt + 64);           // [64]

    const int b   = blockIdx.x;
    const int tid = threadIdx.x;

    // neighbor indices; zero padding rows of both buffers
    if (tid < K_N) sIdx[tid] = act_users[(size_t)b * K_N + tid];
    for (int idx = tid; idx < (ROWS_PAD - K_N) * ASTR; idx += 256) {
        int r = K_N + idx / ASTR;
        int c = idx % ASTR;
        bufA[r * ASTR + c] = 0.f;
        bufB[r * ASTR + c] = 0.f;
    }
    // bias for layer 1 (fusion)
    if (tid < 128) sVec[tid] = b_fus[tid];
    __syncthreads();

    // gather: bufA[k] = emb row, bufB[k] = profile row (float4, coalesced)
    for (int idx = tid; idx < K_N * 64; idx += 256) {
        int k = idx >> 6;
        int q = idx & 63;
        int u = sIdx[k];
        if (q < 32) {
            *(float4*)(bufA + k * ASTR + q * 4) =
                *(const float4*)(emb_table + (size_t)u * 128 + q * 4);
        } else {
            *(float4*)(bufB + k * ASTR + (q - 32) * 4) =
                *(const float4*)(prof_table + (size_t)u * 128 + (q - 32) * 4);
        }
    }

    // L1: fused = relu([emb|prof] @ w_fus + b_fus)       -> bufA
    gemm50(w_fus, 4, bufA, bufB, sVec, bufA, sW, tid);
    __syncthreads();

    // prep: sVec = i_emb @ w_c1[128:256] + b_c1
    if (tid < 32) {
        float4 v = *(const float4*)(i_embs + (size_t)b * 128 + tid * 4);
        *(float4*)(sX + tid * 4) = v;
    }
    __syncthreads();
    prep_vec_matvec(w_c1 + (size_t)128 * 128, b_c1, sX, sVec, sW, tid);

    // L2: c1 = relu(fused @ w_c1_top + sVec)             -> bufB
    gemm50(w_c1, 2, bufA, nullptr, sVec, bufB, sW, tid);
    __syncthreads();

    if (tid < 128) sVec[tid] = b_c2[tid];
    // L3: coup = relu(c1 @ w_c2 + b_c2)                  -> bufA   (kept!)
    gemm50(w_c2, 2, bufB, nullptr, sVec, bufA, sW, tid);
    __syncthreads();

    // prep: sVec = u_emb @ w_a1[128:256] + b_a1
    if (tid < 32) {
        float4 v = *(const float4*)(u_embs + (size_t)b * 128 + tid * 4);
        *(float4*)(sX + tid * 4) = v;
    }
    __syncthreads();
    prep_vec_matvec(w_a1 + (size_t)128 * 128, b_a1, sX, sVec, sW, tid);

    // L4: h = relu(coup @ w_a1_top + sVec)               -> bufB
    gemm50(w_a1, 2, bufA, nullptr, sVec, bufB, sW, tid);
    __syncthreads();

    if (tid < 128) sVec[tid] = b_a2[tid];
    // L5: h2 = relu(h @ w_a2 + b_a2)                     -> bufB (in-place OK)
    gemm50(w_a2, 2, bufB, nullptr, sVec, bufB, sW, tid);
    __syncthreads();

    // L6: scores[k] = h2[k] . w_a3 + b_a3    (warp per k)
    {
        int warp = tid >> 5, lane = tid & 31;
        for (int k = warp; k < K_N; k += 8) {
            float p = 0.f;
#pragma unroll
            for (int t = 0; t < 4; ++t) {
                int i = lane + 32 * t;
                p = fmaf(bufB[k * ASTR + i], w_a3[i], p);
            }
#pragma unroll
            for (int o = 16; o; o >>= 1)
                p += __shfl_xor_sync(0xffffffffu, p, o);
            if (lane == 0) sScore[k] = p + b_a3[0];
        }
    }
    __syncthreads();

    // softmax over 50 scores (warp 0)
    if (tid < 32) {
        float v1 = (tid < K_N)      ? sScore[tid]      : -1e30f;
        float v2 = (tid + 32 < K_N) ? sScore[tid + 32] : -1e30f;
        float m = fmaxf(v1, v2);
#pragma unroll
        for (int o = 16; o; o >>= 1)
            m = fmaxf(m, __shfl_xor_sync(0xffffffffu, m, o));
        float e1 = (tid < K_N)      ? expf(v1 - m) : 0.f;
        float e2 = (tid + 32 < K_N) ? expf(v2 - m) : 0.f;
        float s = e1 + e2;
#pragma unroll
        for (int o = 16; o; o >>= 1)
            s += __shfl_xor_sync(0xffffffffu, s, o);
        float inv = 1.f / s;
        if (tid < K_N)      sAtt[tid]      = e1 * inv;
        if (tid + 32 < K_N) sAtt[tid + 32] = e2 * inv;
    }
    __syncthreads();

    // combined[e] = sum_k att[k] * coup[k][e]   (coup in bufA)
    if (tid < 128) {
        float s = 0.f;
#pragma unroll
        for (int k = 0; k < K_N; ++k)
            s = fmaf(sAtt[k], bufA[k * ASTR + tid], s);
        out_combined[(size_t)b * 128 + tid] = s;
    }
    if (tid >= 128 && tid < 128 + K_N)
        out_att[(size_t)b * K_N + (tid - 128)] = sAtt[tid - 128];
}

extern "C" void kernel_launch(void* const* d_in, const int* in_sizes, int n_in,
                              void* d_out, int out_size) {
    const float* u_embs = (const float*)d_in[1];
    const float* i_embs = (const float*)d_in[3];
    const int*   act    = (const int*)d_in[4];
    const float* table  = (const float*)d_in[5];
    const float* prof   = (const float*)d_in[6];
    const float* w_fus  = (const float*)d_in[7];
    const float* b_fus  = (const float*)d_in[8];
    const float* w_c1   = (const float*)d_in[9];
    const float* b_c1   = (const float*)d_in[10];
    const float* w_c2   = (const float*)d_in[11];
    const float* b_c2   = (const float*)d_in[12];
    const float* w_a1   = (const float*)d_in[13];
    const float* b_a1   = (const float*)d_in[14];
    const float* w_a2   = (const float*)d_in[15];
    const float* b_a2   = (const float*)d_in[16];
    const float* w_a3   = (const float*)d_in[17];
    const float* b_a3   = (const float*)d_in[18];

    int B = in_sizes[0];   // 4096

    float* out_combined = (float*)d_out;
    float* out_att      = out_combined + (size_t)B * E_N;

    size_t smem_bytes = (size_t)(2 * ROWS_PAD * ASTR + 64 * WSTR + 128 + 128 + 192)
                        * sizeof(float);
    cudaFuncSetAttribute(influence_kernel,
                         cudaFuncAttributeMaxDynamicSharedMemorySize,
                         (int)smem_bytes);

    influence_kernel<<<B, 256, smem_bytes>>>(
        u_embs, i_embs, act, table, prof,
        w_fus, b_fus, w_c1, b_c1, w_c2, b_c2,
        w_a1, b_a1, w_a2, b_a2, w_a3, b_a3,
        out_combined, out_att);
}